// round 6
// baseline (speedup 1.0000x reference)
#include <cuda_runtime.h>
#include <cuda_bf16.h>
#include <math.h>
#include <stdint.h>

// Problem constants (fixed shapes from setup_inputs)
#define BATCH 4
#define SEQ   2048
#define DMODEL 1024
#define NHEADS 16
#define FDIM  16
#define HDIM  64
#define NTOK  (BATCH*SEQ)          // 8192
#define QKDIM (NHEADS*FDIM)        // 256
#define VDIM  (NHEADS*HDIM)        // 1024
#define FEAT  273                  // 1 + 16 + 256
#define NCHUNK 16                  // 2048 / 128
#define CHUNK 128
#define KV_ELEMS (BATCH*NHEADS*HDIM*FEAT)   // 1,118,208
#define OUT_ELEMS (NTOK*DMODEL)             // 8,388,608
#define SDF (FEAT*HDIM)            // 17472

// Scratch (device globals; no runtime allocation)
__device__ float g_Q[NTOK*QKDIM];
__device__ float g_K[NTOK*QKDIM];
__device__ float g_V[NTOK*VDIM];
__device__ float g_Y[NTOK*VDIM];
__device__ float g_DS[64*NCHUNK*SDF];

__device__ __forceinline__ uint32_t f2tf32(float x) {
    uint32_t u;
    asm("cvt.rna.tf32.f32 %0, %1;" : "=r"(u) : "f"(x));
    return u;
}

// ---------------------------------------------------------------------------
// TF32 tensor-core GEMM: C[M,N] = A[M,K] @ B[N,K]^T (row-major, K contiguous)
// 128x128 block, 4 warps of 64x64, BK=16, 2-stage double-buffered smem.
// k-permuted smem rows: s(k) = (k&3)*4 + (k>>2) so each lane's 4 needed
// k-values are contiguous -> LDS.128 fragment loads covering BOTH K=8 steps.
// ---------------------------------------------------------------------------
#define GPAD 20
__global__ __launch_bounds__(128)
void tgemm_nt(const float* __restrict__ A, const float* __restrict__ B,
              float* __restrict__ C, int M, int N, int K) {
    __shared__ uint32_t As[2][128][GPAD];
    __shared__ uint32_t Bs[2][128][GPAD];
    const int tid  = threadIdx.x;
    const int warp = tid >> 5, lane = tid & 31;
    const int gid  = lane >> 2, tig = lane & 3;
    const int wm = (warp >> 1) * 64, wn = (warp & 1) * 64;
    const int bm = blockIdx.x * 128, bn = blockIdx.y * 128;

    // loader mapping: row = (tid>>2) + 32p, k chunk = (tid&3)*4
    const int lr = tid >> 2;
    const int cperm = tid & 3;                 // permuted column sub-index
    const float* Ap = A + (size_t)(bm + lr) * K + cperm * 4;
    const float* Bp = B + (size_t)(bn + lr) * K + cperm * 4;
    const size_t row32 = (size_t)32 * K;

    float acc[4][8][4];
#pragma unroll
    for (int mt = 0; mt < 4; mt++)
#pragma unroll
        for (int nt = 0; nt < 8; nt++)
#pragma unroll
            for (int e = 0; e < 4; e++) acc[mt][nt][e] = 0.f;

    float4 ar[4], br[4];
#pragma unroll
    for (int p = 0; p < 4; p++) {
        ar[p] = *(const float4*)(Ap + p * row32);
        br[p] = *(const float4*)(Bp + p * row32);
    }
#pragma unroll
    for (int p = 0; p < 4; p++) {
        uint32_t* as = &As[0][lr + p * 32][0];
        as[0 * 4 + cperm] = f2tf32(ar[p].x);
        as[1 * 4 + cperm] = f2tf32(ar[p].y);
        as[2 * 4 + cperm] = f2tf32(ar[p].z);
        as[3 * 4 + cperm] = f2tf32(ar[p].w);
        uint32_t* bs = &Bs[0][lr + p * 32][0];
        bs[0 * 4 + cperm] = f2tf32(br[p].x);
        bs[1 * 4 + cperm] = f2tf32(br[p].y);
        bs[2 * 4 + cperm] = f2tf32(br[p].z);
        bs[3 * 4 + cperm] = f2tf32(br[p].w);
    }
    __syncthreads();

    int cur = 0;
    for (int k0 = 0; k0 < K; k0 += 16) {
        const bool more = (k0 + 16 < K);
        if (more) {
#pragma unroll
            for (int p = 0; p < 4; p++) {
                ar[p] = *(const float4*)(Ap + k0 + 16 + p * row32);
                br[p] = *(const float4*)(Bp + k0 + 16 + p * row32);
            }
        }

        // fragment loads: one LDS.128 per row covers both K=8 steps
        uint32_t af[4][2][4], bf[8][4];
#pragma unroll
        for (int mt = 0; mt < 4; mt++) {
            const int m = wm + mt * 16 + gid;
            *(uint4*)af[mt][0] = *(const uint4*)&As[cur][m][tig * 4];
            *(uint4*)af[mt][1] = *(const uint4*)&As[cur][m + 8][tig * 4];
        }
#pragma unroll
        for (int nt = 0; nt < 8; nt++) {
            const int n = wn + nt * 8 + gid;
            *(uint4*)bf[nt] = *(const uint4*)&Bs[cur][n][tig * 4];
        }
#pragma unroll
        for (int ks = 0; ks < 2; ks++) {
#pragma unroll
            for (int mt = 0; mt < 4; mt++)
#pragma unroll
                for (int nt = 0; nt < 8; nt++) {
                    asm volatile(
                        "mma.sync.aligned.m16n8k8.row.col.f32.tf32.tf32.f32 "
                        "{%0,%1,%2,%3}, {%4,%5,%6,%7}, {%8,%9}, {%0,%1,%2,%3};"
                        : "+f"(acc[mt][nt][0]), "+f"(acc[mt][nt][1]),
                          "+f"(acc[mt][nt][2]), "+f"(acc[mt][nt][3])
                        : "r"(af[mt][0][2 * ks]), "r"(af[mt][1][2 * ks]),
                          "r"(af[mt][0][2 * ks + 1]), "r"(af[mt][1][2 * ks + 1]),
                          "r"(bf[nt][2 * ks]), "r"(bf[nt][2 * ks + 1]));
                }
        }

        if (more) {
            const int nxt = cur ^ 1;
            __syncthreads();
#pragma unroll
            for (int p = 0; p < 4; p++) {
                uint32_t* as = &As[nxt][lr + p * 32][0];
                as[0 * 4 + cperm] = f2tf32(ar[p].x);
                as[1 * 4 + cperm] = f2tf32(ar[p].y);
                as[2 * 4 + cperm] = f2tf32(ar[p].z);
                as[3 * 4 + cperm] = f2tf32(ar[p].w);
                uint32_t* bs = &Bs[nxt][lr + p * 32][0];
                bs[0 * 4 + cperm] = f2tf32(br[p].x);
                bs[1 * 4 + cperm] = f2tf32(br[p].y);
                bs[2 * 4 + cperm] = f2tf32(br[p].z);
                bs[3 * 4 + cperm] = f2tf32(br[p].w);
            }
            __syncthreads();
        }
        cur ^= 1;
    }

    // epilogue
#pragma unroll
    for (int mt = 0; mt < 4; mt++) {
        const int r0 = bm + wm + mt * 16 + gid;
#pragma unroll
        for (int nt = 0; nt < 8; nt++) {
            const int cc = bn + wn + nt * 8 + tig * 2;
            *(float2*)&C[(size_t)r0 * N + cc] =
                make_float2(acc[mt][nt][0], acc[mt][nt][1]);
            *(float2*)&C[(size_t)(r0 + 8) * N + cc] =
                make_float2(acc[mt][nt][2], acc[mt][nt][3]);
        }
    }
}

// ---------------------------------------------------------------------------
// Kernel A: per-chunk state increment  DS[bh,ck,d,f] = sum_{n in chunk} kf[n,d] v[n,f]
// Split over blockIdx.z (f-halves of 32) for occupancy. thread=(i 0..15, fq 0..15)
// ---------------------------------------------------------------------------
__global__ __launch_bounds__(256, 3)
void state_kernel(const float* __restrict__ Km, const float* __restrict__ V,
                  float* __restrict__ DS) {
    __shared__ float ks[32][16];
    __shared__ float vs[32][32];
    const int ck = blockIdx.x;
    const int bh = blockIdx.y;
    const int fh = blockIdx.z;           // 0 or 1: f half
    const int b = bh >> 4, h = bh & 15;
    const int tid = threadIdx.x;
    const int i = tid >> 4;
    const int fq = tid & 15;             // f pair index within half
    const int tokb = b * SEQ + ck * CHUNK;
    const int fbase = fh * 32;

    float m2[16][2];
#pragma unroll
    for (int j = 0; j < 16; j++) { m2[j][0] = 0.f; m2[j][1] = 0.f; }
    float m1[2] = {0.f, 0.f};
    float s0[2] = {0.f, 0.f};

    for (int nb = 0; nb < CHUNK; nb += 32) {
        __syncthreads();
        for (int t = tid; t < 128; t += 256) {
            int r = t >> 2, c4 = (t & 3) << 2;
            *(float4*)&ks[r][c4] =
                *(const float4*)&Km[(size_t)(tokb + nb + r) * QKDIM + h * FDIM + c4];
        }
        {
            int r = tid >> 3, c4 = (tid & 7) << 2;
            *(float4*)&vs[r][c4] =
                *(const float4*)&V[(size_t)(tokb + nb + r) * VDIM + h * HDIM + fbase + c4];
        }
        __syncthreads();
#pragma unroll 4
        for (int r = 0; r < 32; r++) {
            const float ki = ks[r][i];
            const float2 v2 = *(const float2*)&vs[r][fq * 2];
            m1[0] = fmaf(ki, v2.x, m1[0]);
            m1[1] = fmaf(ki, v2.y, m1[1]);
            if (i == 0) { s0[0] += v2.x; s0[1] += v2.y; }
#pragma unroll
            for (int j = 0; j < 16; j++) {
                const float kk = ki * ks[r][j];
                m2[j][0] = fmaf(kk, v2.x, m2[j][0]);
                m2[j][1] = fmaf(kk, v2.y, m2[j][1]);
            }
        }
    }

    float* base = DS + (size_t)(bh * NCHUNK + ck) * SDF;
    const float c2 = 0.17677669529663687f;   // 1/(4*sqrt(2))
#pragma unroll
    for (int ff = 0; ff < 2; ff++) {
        const int f = fbase + fq * 2 + ff;
#pragma unroll
        for (int j = 0; j < 16; j++)
            base[(17 + i * 16 + j) * HDIM + f] = m2[j][ff] * c2;
        base[(1 + i) * HDIM + f] = m1[ff] * 0.5f;
        if (i == 0) base[f] = s0[ff];
    }
}

// ---------------------------------------------------------------------------
// Kernel B: in-place exclusive scan over chunk states; inclusive total -> kv_state
// ---------------------------------------------------------------------------
__global__ void scan_kernel(float* __restrict__ DS, float* __restrict__ kv_out) {
    const int bh = blockIdx.y;
    const int e = blockIdx.x * 256 + threadIdx.x;
    if (e >= SDF) return;
    size_t base = (size_t)bh * NCHUNK * SDF + e;
    float run = 0.f;
#pragma unroll
    for (int c = 0; c < NCHUNK; c++) {
        float v = DS[base + (size_t)c * SDF];
        DS[base + (size_t)c * SDF] = run;
        run += v;
    }
    if (kv_out) {
        const int d = e >> 6, f = e & 63;
        kv_out[(size_t)bh * (HDIM * FEAT) + f * FEAT + d] = run;
    }
}

// ---------------------------------------------------------------------------
// Kernel C: y = qf . S_prev  +  intra-chunk causal, fused RMSNorm + g.
// ---------------------------------------------------------------------------
__global__ __launch_bounds__(256, 2)
void attn_out_kernel(const float* __restrict__ Q, const float* __restrict__ Km,
                     const float* __restrict__ V, const float* __restrict__ Sprev,
                     const float* __restrict__ g, float* __restrict__ Y) {
    __shared__ float Qs[128][16];
    __shared__ float Kc[128][16];
    __shared__ float Vc[128][64];
    __shared__ float Ss[17][64];
    __shared__ float gs[64];
    const int ck = blockIdx.x;
    const int bh = blockIdx.y;
    const int b = bh >> 4, h = bh & 15;
    const int tid = threadIdx.x;
    const int fg = tid & 7, tg = tid >> 3;
    const int f0 = fg * 8;
    const int t0 = tg * 4;
    const int tok0 = b * SEQ + ck * CHUNK;
    const float SC  = 0.4204482076268573f;
    const float LIN = 1.1892071150027210f;
    const float DOT = 2.3784142300054421f;

    for (int t = tid; t < 512; t += 256) {
        int r = t >> 2, c4 = (t & 3) << 2;
        float4 qv = *(const float4*)&Q[(size_t)(tok0 + r) * QKDIM + h * FDIM + c4];
        Qs[r][c4 + 0] = qv.x * SC; Qs[r][c4 + 1] = qv.y * SC;
        Qs[r][c4 + 2] = qv.z * SC; Qs[r][c4 + 3] = qv.w * SC;
        *(float4*)&Kc[r][c4] =
            *(const float4*)&Km[(size_t)(tok0 + r) * QKDIM + h * FDIM + c4];
    }
    for (int t = tid; t < 2048; t += 256) {
        int r = t >> 4, c4 = (t & 15) << 2;
        *(float4*)&Vc[r][c4] =
            *(const float4*)&V[(size_t)(tok0 + r) * VDIM + h * HDIM + c4];
    }
    if (tid < 64) gs[tid] = g[tid];
    const float* Sp = Sprev + (size_t)(bh * NCHUNK + ck) * SDF;
    for (int t = tid; t < 272; t += 256) {
        int r = t >> 4, c4 = (t & 15) << 2;
        *(float4*)&Ss[r][c4] = *(const float4*)&Sp[r * HDIM + c4];
    }
    __syncthreads();

    float acc[4][8];
    {
        float sv[8];
        *(float4*)&sv[0] = *(const float4*)&Ss[0][f0];
        *(float4*)&sv[4] = *(const float4*)&Ss[0][f0 + 4];
#pragma unroll
        for (int t = 0; t < 4; t++)
#pragma unroll
            for (int f = 0; f < 8; f++) acc[t][f] = sv[f];
#pragma unroll
        for (int j = 0; j < 16; j++) {
            *(float4*)&sv[0] = *(const float4*)&Ss[1 + j][f0];
            *(float4*)&sv[4] = *(const float4*)&Ss[1 + j][f0 + 4];
#pragma unroll
            for (int t = 0; t < 4; t++) {
                const float m = Qs[t0 + t][j] * LIN;
#pragma unroll
                for (int f = 0; f < 8; f++) acc[t][f] = fmaf(m, sv[f], acc[t][f]);
            }
        }
    }

    for (int i = 0; i < 16; i++) {
        __syncthreads();
        {
            int r = tid >> 4, c4 = (tid & 15) << 2;
            *(float4*)&Ss[r][c4] =
                *(const float4*)&Sp[(17 + i * 16 + r) * HDIM + c4];
        }
        __syncthreads();
        float qi[4];
#pragma unroll
        for (int t = 0; t < 4; t++) qi[t] = Qs[t0 + t][i];
#pragma unroll
        for (int j = 0; j < 16; j++) {
            float sv[8];
            *(float4*)&sv[0] = *(const float4*)&Ss[j][f0];
            *(float4*)&sv[4] = *(const float4*)&Ss[j][f0 + 4];
#pragma unroll
            for (int t = 0; t < 4; t++) {
                const float m = qi[t] * Qs[t0 + t][j];
#pragma unroll
                for (int f = 0; f < 8; f++) acc[t][f] = fmaf(m, sv[f], acc[t][f]);
            }
        }
    }

    float qr[4][16];
#pragma unroll
    for (int t = 0; t < 4; t++)
#pragma unroll
        for (int i = 0; i < 16; i++) qr[t][i] = Qs[t0 + t][i];

    const int mEnd = ((tid >> 5) + 1) * 16;
    for (int m = 0; m < mEnd; m++) {
        float s[4] = {0.f, 0.f, 0.f, 0.f};
#pragma unroll
        for (int i = 0; i < 16; i++) {
            const float ki = Kc[m][i];
            s[0] = fmaf(qr[0][i], ki, s[0]);
            s[1] = fmaf(qr[1][i], ki, s[1]);
            s[2] = fmaf(qr[2][i], ki, s[2]);
            s[3] = fmaf(qr[3][i], ki, s[3]);
        }
        float a[4];
#pragma unroll
        for (int t = 0; t < 4; t++) {
            const float sd = s[t] * DOT;
            float av = fmaf(sd, 0.25f, 1.0f);
            av = fmaf(sd * sd, 0.03125f, av);
            a[t] = (m <= t0 + t) ? av : 0.f;
        }
        float v[8];
        *(float4*)&v[0] = *(const float4*)&Vc[m][f0];
        *(float4*)&v[4] = *(const float4*)&Vc[m][f0 + 4];
#pragma unroll
        for (int t = 0; t < 4; t++)
#pragma unroll
            for (int f = 0; f < 8; f++)
                acc[t][f] = fmaf(a[t], v[f], acc[t][f]);
    }

#pragma unroll
    for (int t = 0; t < 4; t++) {
        float ss = 0.f;
#pragma unroll
        for (int f = 0; f < 8; f++) ss = fmaf(acc[t][f], acc[t][f], ss);
        ss += __shfl_xor_sync(0xffffffffu, ss, 1);
        ss += __shfl_xor_sync(0xffffffffu, ss, 2);
        ss += __shfl_xor_sync(0xffffffffu, ss, 4);
        const float rms = rsqrtf(ss * (1.0f / 64.0f) + 1e-5f);
        float* yp = Y + (size_t)(tok0 + t0 + t) * VDIM + h * HDIM + f0;
        float4 o0, o1;
        o0.x = acc[t][0] * rms * gs[f0 + 0];
        o0.y = acc[t][1] * rms * gs[f0 + 1];
        o0.z = acc[t][2] * rms * gs[f0 + 2];
        o0.w = acc[t][3] * rms * gs[f0 + 3];
        o1.x = acc[t][4] * rms * gs[f0 + 4];
        o1.y = acc[t][5] * rms * gs[f0 + 5];
        o1.z = acc[t][6] * rms * gs[f0 + 6];
        o1.w = acc[t][7] * rms * gs[f0 + 7];
        *(float4*)&yp[0] = o0;
        *(float4*)&yp[4] = o1;
    }
}

// ---------------------------------------------------------------------------
extern "C" void kernel_launch(void* const* d_in, const int* in_sizes, int n_in,
                              void* d_out, int out_size) {
    const float* X  = (const float*)d_in[0];
    const float* Wq = (const float*)d_in[1];
    const float* Wk = (const float*)d_in[2];
    const float* Wv = (const float*)d_in[3];
    const float* Wo = (const float*)d_in[4];
    const float* g  = (const float*)d_in[5];
    float* out = (float*)d_out;

    float *Qb, *Kb, *Vb, *Yb, *Sb;
    cudaGetSymbolAddress((void**)&Qb, g_Q);
    cudaGetSymbolAddress((void**)&Kb, g_K);
    cudaGetSymbolAddress((void**)&Vb, g_V);
    cudaGetSymbolAddress((void**)&Yb, g_Y);
    cudaGetSymbolAddress((void**)&Sb, g_DS);

    // Projections (tf32 mma.sync, k-permuted fragment loads)
    tgemm_nt<<<dim3(NTOK / 128, QKDIM / 128), 128>>>(X, Wq, Qb, NTOK, QKDIM, DMODEL);
    tgemm_nt<<<dim3(NTOK / 128, QKDIM / 128), 128>>>(X, Wk, Kb, NTOK, QKDIM, DMODEL);
    tgemm_nt<<<dim3(NTOK / 128, VDIM / 128),  128>>>(X, Wv, Vb, NTOK, VDIM,  DMODEL);

    // Chunked linear attention
    float* kv_out = (out_size >= OUT_ELEMS + KV_ELEMS) ? (out + OUT_ELEMS) : nullptr;
    state_kernel<<<dim3(NCHUNK, BATCH * NHEADS, 2), 256>>>(Kb, Vb, Sb);
    scan_kernel<<<dim3((SDF + 255) / 256, BATCH * NHEADS), 256>>>(Sb, kv_out);
    attn_out_kernel<<<dim3(NCHUNK, BATCH * NHEADS), 256>>>(Qb, Kb, Vb, Sb, g, Yb);

    // Output projection (tf32 mma.sync)
    tgemm_nt<<<dim3(NTOK / 128, DMODEL / 128), 128>>>(Yb, Wo, out, NTOK, DMODEL, DMODEL);
}

// round 7
// speedup vs baseline: 1.1053x; 1.1053x over previous
#include <cuda_runtime.h>
#include <cuda_bf16.h>
#include <math.h>
#include <stdint.h>

// Problem constants (fixed shapes from setup_inputs)
#define BATCH 4
#define SEQ   2048
#define DMODEL 1024
#define NHEADS 16
#define FDIM  16
#define HDIM  64
#define NTOK  (BATCH*SEQ)          // 8192
#define QKDIM (NHEADS*FDIM)        // 256
#define VDIM  (NHEADS*HDIM)        // 1024
#define FEAT  273                  // 1 + 16 + 256
#define NCHUNK 16                  // 2048 / 128
#define CHUNK 128
#define KV_ELEMS (BATCH*NHEADS*HDIM*FEAT)   // 1,118,208
#define OUT_ELEMS (NTOK*DMODEL)             // 8,388,608
#define SDF (FEAT*HDIM)            // 17472

// Scratch (device globals; no runtime allocation)
__device__ float g_Q[NTOK*QKDIM];
__device__ float g_K[NTOK*QKDIM];
__device__ float g_V[NTOK*VDIM];
__device__ float g_Y[NTOK*VDIM];
__device__ float g_DS[64*NCHUNK*SDF];

__device__ __forceinline__ uint32_t f2tf32(float x) {
    uint32_t u;
    asm("cvt.rna.tf32.f32 %0, %1;" : "=r"(u) : "f"(x));
    return u;
}

// ---------------------------------------------------------------------------
// Shared tf32 GEMM tile body (R4 design): 128x128 block, 4 warps of 64x64,
// BK=16, double-buffered smem [k][row] pad 20, one sync per K-tile.
// ---------------------------------------------------------------------------
#define GPAD 20
struct GSmem {
    uint32_t As[2][16][132];
    uint32_t Bs[2][16][132];
};

__device__ __forceinline__ void gemm_tile(
    const float* __restrict__ A, const float* __restrict__ B,
    float* __restrict__ C, int N, int K, int bm, int bn, GSmem& sm) {
    const int tid  = threadIdx.x;
    const int warp = tid >> 5, lane = tid & 31;
    const int gid  = lane >> 2, tig = lane & 3;
    const int wm = (warp >> 1) * 64, wn = (warp & 1) * 64;

    const int lr = tid >> 2;
    const int kc = (tid & 3) << 2;
    const float* Ap = A + (size_t)(bm + lr) * K + kc;
    const float* Bp = B + (size_t)(bn + lr) * K + kc;
    const size_t row32 = (size_t)32 * K;

    float acc[4][8][4];
#pragma unroll
    for (int mt = 0; mt < 4; mt++)
#pragma unroll
        for (int nt = 0; nt < 8; nt++)
#pragma unroll
            for (int e = 0; e < 4; e++) acc[mt][nt][e] = 0.f;

    float4 ar[4], br[4];
#pragma unroll
    for (int p = 0; p < 4; p++) {
        ar[p] = *(const float4*)(Ap + p * row32);
        br[p] = *(const float4*)(Bp + p * row32);
    }
#pragma unroll
    for (int p = 0; p < 4; p++) {
        sm.As[0][kc + 0][lr + p * 32] = f2tf32(ar[p].x);
        sm.As[0][kc + 1][lr + p * 32] = f2tf32(ar[p].y);
        sm.As[0][kc + 2][lr + p * 32] = f2tf32(ar[p].z);
        sm.As[0][kc + 3][lr + p * 32] = f2tf32(ar[p].w);
        sm.Bs[0][kc + 0][lr + p * 32] = f2tf32(br[p].x);
        sm.Bs[0][kc + 1][lr + p * 32] = f2tf32(br[p].y);
        sm.Bs[0][kc + 2][lr + p * 32] = f2tf32(br[p].z);
        sm.Bs[0][kc + 3][lr + p * 32] = f2tf32(br[p].w);
    }
    __syncthreads();

    int cur = 0;
    for (int k0 = 0; k0 < K; k0 += 16) {
        const bool more = (k0 + 16 < K);
        if (more) {
#pragma unroll
            for (int p = 0; p < 4; p++) {
                ar[p] = *(const float4*)(Ap + k0 + 16 + p * row32);
                br[p] = *(const float4*)(Bp + k0 + 16 + p * row32);
            }
        }

#pragma unroll
        for (int ks = 0; ks < 2; ks++) {
            const int kk = ks * 8;
            uint32_t af[4][4], bf[8][2];
#pragma unroll
            for (int mt = 0; mt < 4; mt++) {
                const int m = wm + mt * 16 + gid;
                af[mt][0] = sm.As[cur][kk + tig][m];
                af[mt][1] = sm.As[cur][kk + tig][m + 8];
                af[mt][2] = sm.As[cur][kk + tig + 4][m];
                af[mt][3] = sm.As[cur][kk + tig + 4][m + 8];
            }
#pragma unroll
            for (int nt = 0; nt < 8; nt++) {
                const int n = wn + nt * 8 + gid;
                bf[nt][0] = sm.Bs[cur][kk + tig][n];
                bf[nt][1] = sm.Bs[cur][kk + tig + 4][n];
            }
#pragma unroll
            for (int mt = 0; mt < 4; mt++)
#pragma unroll
                for (int nt = 0; nt < 8; nt++) {
                    asm volatile(
                        "mma.sync.aligned.m16n8k8.row.col.f32.tf32.tf32.f32 "
                        "{%0,%1,%2,%3}, {%4,%5,%6,%7}, {%8,%9}, {%0,%1,%2,%3};"
                        : "+f"(acc[mt][nt][0]), "+f"(acc[mt][nt][1]),
                          "+f"(acc[mt][nt][2]), "+f"(acc[mt][nt][3])
                        : "r"(af[mt][0]), "r"(af[mt][1]),
                          "r"(af[mt][2]), "r"(af[mt][3]),
                          "r"(bf[nt][0]), "r"(bf[nt][1]));
                }
        }

        if (more) {
            const int nxt = cur ^ 1;
#pragma unroll
            for (int p = 0; p < 4; p++) {
                sm.As[nxt][kc + 0][lr + p * 32] = f2tf32(ar[p].x);
                sm.As[nxt][kc + 1][lr + p * 32] = f2tf32(ar[p].y);
                sm.As[nxt][kc + 2][lr + p * 32] = f2tf32(ar[p].z);
                sm.As[nxt][kc + 3][lr + p * 32] = f2tf32(ar[p].w);
                sm.Bs[nxt][kc + 0][lr + p * 32] = f2tf32(br[p].x);
                sm.Bs[nxt][kc + 1][lr + p * 32] = f2tf32(br[p].y);
                sm.Bs[nxt][kc + 2][lr + p * 32] = f2tf32(br[p].z);
                sm.Bs[nxt][kc + 3][lr + p * 32] = f2tf32(br[p].w);
            }
            __syncthreads();
        }
        cur ^= 1;
    }

#pragma unroll
    for (int mt = 0; mt < 4; mt++) {
        const int r0 = bm + wm + mt * 16 + gid;
#pragma unroll
        for (int nt = 0; nt < 8; nt++) {
            const int cc = bn + wn + nt * 8 + tig * 2;
            *(float2*)&C[(size_t)r0 * N + cc] =
                make_float2(acc[mt][nt][0], acc[mt][nt][1]);
            *(float2*)&C[(size_t)(r0 + 8) * N + cc] =
                make_float2(acc[mt][nt][2], acc[mt][nt][3]);
        }
    }
}

// Fused Q/K/V projection: grid (NTOK/128, 12). y<2: Q, y<4: K, else: V.
__global__ __launch_bounds__(128)
void qkv_gemm(const float* __restrict__ X,
              const float* __restrict__ Wq, const float* __restrict__ Wk,
              const float* __restrict__ Wv,
              float* __restrict__ Qb, float* __restrict__ Kb,
              float* __restrict__ Vb) {
    __shared__ GSmem sm;
    const int y = blockIdx.y;
    const float* B;
    float* C;
    int N, bn;
    if (y < 2)      { B = Wq; C = Qb; N = QKDIM; bn = y * 128; }
    else if (y < 4) { B = Wk; C = Kb; N = QKDIM; bn = (y - 2) * 128; }
    else            { B = Wv; C = Vb; N = VDIM;  bn = (y - 4) * 128; }
    gemm_tile(X, B, C, N, DMODEL, blockIdx.x * 128, bn, sm);
}

// Generic GEMM (output projection): C[M,N] = A @ B^T
__global__ __launch_bounds__(128)
void tgemm_nt(const float* __restrict__ A, const float* __restrict__ B,
              float* __restrict__ C, int M, int N, int K) {
    __shared__ GSmem sm;
    gemm_tile(A, B, C, N, K, blockIdx.x * 128, blockIdx.y * 128, sm);
}

// ---------------------------------------------------------------------------
// Kernel A: per-chunk state increment, f split over blockIdx.z for occupancy
// ---------------------------------------------------------------------------
__global__ __launch_bounds__(256, 3)
void state_kernel(const float* __restrict__ Km, const float* __restrict__ V,
                  float* __restrict__ DS) {
    __shared__ float ks[32][16];
    __shared__ float vs[32][32];
    const int ck = blockIdx.x;
    const int bh = blockIdx.y;
    const int fh = blockIdx.z;
    const int b = bh >> 4, h = bh & 15;
    const int tid = threadIdx.x;
    const int i = tid >> 4;
    const int fq = tid & 15;
    const int tokb = b * SEQ + ck * CHUNK;
    const int fbase = fh * 32;

    float m2[16][2];
#pragma unroll
    for (int j = 0; j < 16; j++) { m2[j][0] = 0.f; m2[j][1] = 0.f; }
    float m1[2] = {0.f, 0.f};
    float s0[2] = {0.f, 0.f};

    for (int nb = 0; nb < CHUNK; nb += 32) {
        __syncthreads();
        for (int t = tid; t < 128; t += 256) {
            int r = t >> 2, c4 = (t & 3) << 2;
            *(float4*)&ks[r][c4] =
                *(const float4*)&Km[(size_t)(tokb + nb + r) * QKDIM + h * FDIM + c4];
        }
        {
            int r = tid >> 3, c4 = (tid & 7) << 2;
            *(float4*)&vs[r][c4] =
                *(const float4*)&V[(size_t)(tokb + nb + r) * VDIM + h * HDIM + fbase + c4];
        }
        __syncthreads();
#pragma unroll 4
        for (int r = 0; r < 32; r++) {
            const float ki = ks[r][i];
            const float2 v2 = *(const float2*)&vs[r][fq * 2];
            m1[0] = fmaf(ki, v2.x, m1[0]);
            m1[1] = fmaf(ki, v2.y, m1[1]);
            if (i == 0) { s0[0] += v2.x; s0[1] += v2.y; }
#pragma unroll
            for (int j = 0; j < 16; j++) {
                const float kk = ki * ks[r][j];
                m2[j][0] = fmaf(kk, v2.x, m2[j][0]);
                m2[j][1] = fmaf(kk, v2.y, m2[j][1]);
            }
        }
    }

    float* base = DS + (size_t)(bh * NCHUNK + ck) * SDF;
    const float c2 = 0.17677669529663687f;
#pragma unroll
    for (int ff = 0; ff < 2; ff++) {
        const int f = fbase + fq * 2 + ff;
#pragma unroll
        for (int j = 0; j < 16; j++)
            base[(17 + i * 16 + j) * HDIM + f] = m2[j][ff] * c2;
        base[(1 + i) * HDIM + f] = m1[ff] * 0.5f;
        if (i == 0) base[f] = s0[ff];
    }
}

// ---------------------------------------------------------------------------
// Kernel B: exclusive scan over chunk states; inclusive total -> kv_state
// ---------------------------------------------------------------------------
__global__ void scan_kernel(float* __restrict__ DS, float* __restrict__ kv_out) {
    const int bh = blockIdx.y;
    const int e = blockIdx.x * 256 + threadIdx.x;
    if (e >= SDF) return;
    size_t base = (size_t)bh * NCHUNK * SDF + e;
    float run = 0.f;
#pragma unroll
    for (int c = 0; c < NCHUNK; c++) {
        float v = DS[base + (size_t)c * SDF];
        DS[base + (size_t)c * SDF] = run;
        run += v;
    }
    if (kv_out) {
        const int d = e >> 6, f = e & 63;
        kv_out[(size_t)bh * (HDIM * FEAT) + f * FEAT + d] = run;
    }
}

// ---------------------------------------------------------------------------
// Kernel C: y = qf . S_prev + intra-chunk causal, fused RMSNorm + g
// ---------------------------------------------------------------------------
__global__ __launch_bounds__(256, 2)
void attn_out_kernel(const float* __restrict__ Q, const float* __restrict__ Km,
                     const float* __restrict__ V, const float* __restrict__ Sprev,
                     const float* __restrict__ g, float* __restrict__ Y) {
    __shared__ float Qs[128][16];
    __shared__ float Kc[128][16];
    __shared__ float Vc[128][64];
    __shared__ float Ss[17][64];
    __shared__ float gs[64];
    const int ck = blockIdx.x;
    const int bh = blockIdx.y;
    const int b = bh >> 4, h = bh & 15;
    const int tid = threadIdx.x;
    const int fg = tid & 7, tg = tid >> 3;
    const int f0 = fg * 8;
    const int t0 = tg * 4;
    const int tok0 = b * SEQ + ck * CHUNK;
    const float SC  = 0.4204482076268573f;
    const float LIN = 1.1892071150027210f;
    const float DOT = 2.3784142300054421f;

    for (int t = tid; t < 512; t += 256) {
        int r = t >> 2, c4 = (t & 3) << 2;
        float4 qv = *(const float4*)&Q[(size_t)(tok0 + r) * QKDIM + h * FDIM + c4];
        Qs[r][c4 + 0] = qv.x * SC; Qs[r][c4 + 1] = qv.y * SC;
        Qs[r][c4 + 2] = qv.z * SC; Qs[r][c4 + 3] = qv.w * SC;
        *(float4*)&Kc[r][c4] =
            *(const float4*)&Km[(size_t)(tok0 + r) * QKDIM + h * FDIM + c4];
    }
    for (int t = tid; t < 2048; t += 256) {
        int r = t >> 4, c4 = (t & 15) << 2;
        *(float4*)&Vc[r][c4] =
            *(const float4*)&V[(size_t)(tok0 + r) * VDIM + h * HDIM + c4];
    }
    if (tid < 64) gs[tid] = g[tid];
    const float* Sp = Sprev + (size_t)(bh * NCHUNK + ck) * SDF;
    for (int t = tid; t < 272; t += 256) {
        int r = t >> 4, c4 = (t & 15) << 2;
        *(float4*)&Ss[r][c4] = *(const float4*)&Sp[r * HDIM + c4];
    }
    __syncthreads();

    float acc[4][8];
    {
        float sv[8];
        *(float4*)&sv[0] = *(const float4*)&Ss[0][f0];
        *(float4*)&sv[4] = *(const float4*)&Ss[0][f0 + 4];
#pragma unroll
        for (int t = 0; t < 4; t++)
#pragma unroll
            for (int f = 0; f < 8; f++) acc[t][f] = sv[f];
#pragma unroll
        for (int j = 0; j < 16; j++) {
            *(float4*)&sv[0] = *(const float4*)&Ss[1 + j][f0];
            *(float4*)&sv[4] = *(const float4*)&Ss[1 + j][f0 + 4];
#pragma unroll
            for (int t = 0; t < 4; t++) {
                const float m = Qs[t0 + t][j] * LIN;
#pragma unroll
                for (int f = 0; f < 8; f++) acc[t][f] = fmaf(m, sv[f], acc[t][f]);
            }
        }
    }

    for (int i = 0; i < 16; i++) {
        __syncthreads();
        {
            int r = tid >> 4, c4 = (tid & 15) << 2;
            *(float4*)&Ss[r][c4] =
                *(const float4*)&Sp[(17 + i * 16 + r) * HDIM + c4];
        }
        __syncthreads();
        float qi[4];
#pragma unroll
        for (int t = 0; t < 4; t++) qi[t] = Qs[t0 + t][i];
#pragma unroll
        for (int j = 0; j < 16; j++) {
            float sv[8];
            *(float4*)&sv[0] = *(const float4*)&Ss[j][f0];
            *(float4*)&sv[4] = *(const float4*)&Ss[j][f0 + 4];
#pragma unroll
            for (int t = 0; t < 4; t++) {
                const float m = qi[t] * Qs[t0 + t][j];
#pragma unroll
                for (int f = 0; f < 8; f++) acc[t][f] = fmaf(m, sv[f], acc[t][f]);
            }
        }
    }

    float qr[4][16];
#pragma unroll
    for (int t = 0; t < 4; t++)
#pragma unroll
        for (int i = 0; i < 16; i++) qr[t][i] = Qs[t0 + t][i];

    const int mEnd = ((tid >> 5) + 1) * 16;
    for (int m = 0; m < mEnd; m++) {
        float s[4] = {0.f, 0.f, 0.f, 0.f};
#pragma unroll
        for (int i = 0; i < 16; i++) {
            const float ki = Kc[m][i];
            s[0] = fmaf(qr[0][i], ki, s[0]);
            s[1] = fmaf(qr[1][i], ki, s[1]);
            s[2] = fmaf(qr[2][i], ki, s[2]);
            s[3] = fmaf(qr[3][i], ki, s[3]);
        }
        float a[4];
#pragma unroll
        for (int t = 0; t < 4; t++) {
            const float sd = s[t] * DOT;
            float av = fmaf(sd, 0.25f, 1.0f);
            av = fmaf(sd * sd, 0.03125f, av);
            a[t] = (m <= t0 + t) ? av : 0.f;
        }
        float v[8];
        *(float4*)&v[0] = *(const float4*)&Vc[m][f0];
        *(float4*)&v[4] = *(const float4*)&Vc[m][f0 + 4];
#pragma unroll
        for (int t = 0; t < 4; t++)
#pragma unroll
            for (int f = 0; f < 8; f++)
                acc[t][f] = fmaf(a[t], v[f], acc[t][f]);
    }

#pragma unroll
    for (int t = 0; t < 4; t++) {
        float ss = 0.f;
#pragma unroll
        for (int f = 0; f < 8; f++) ss = fmaf(acc[t][f], acc[t][f], ss);
        ss += __shfl_xor_sync(0xffffffffu, ss, 1);
        ss += __shfl_xor_sync(0xffffffffu, ss, 2);
        ss += __shfl_xor_sync(0xffffffffu, ss, 4);
        const float rms = rsqrtf(ss * (1.0f / 64.0f) + 1e-5f);
        float* yp = Y + (size_t)(tok0 + t0 + t) * VDIM + h * HDIM + f0;
        float4 o0, o1;
        o0.x = acc[t][0] * rms * gs[f0 + 0];
        o0.y = acc[t][1] * rms * gs[f0 + 1];
        o0.z = acc[t][2] * rms * gs[f0 + 2];
        o0.w = acc[t][3] * rms * gs[f0 + 3];
        o1.x = acc[t][4] * rms * gs[f0 + 4];
        o1.y = acc[t][5] * rms * gs[f0 + 5];
        o1.z = acc[t][6] * rms * gs[f0 + 6];
        o1.w = acc[t][7] * rms * gs[f0 + 7];
        *(float4*)&yp[0] = o0;
        *(float4*)&yp[4] = o1;
    }
}

// ---------------------------------------------------------------------------
extern "C" void kernel_launch(void* const* d_in, const int* in_sizes, int n_in,
                              void* d_out, int out_size) {
    const float* X  = (const float*)d_in[0];
    const float* Wq = (const float*)d_in[1];
    const float* Wk = (const float*)d_in[2];
    const float* Wv = (const float*)d_in[3];
    const float* Wo = (const float*)d_in[4];
    const float* g  = (const float*)d_in[5];
    float* out = (float*)d_out;

    float *Qb, *Kb, *Vb, *Yb, *Sb;
    cudaGetSymbolAddress((void**)&Qb, g_Q);
    cudaGetSymbolAddress((void**)&Kb, g_K);
    cudaGetSymbolAddress((void**)&Vb, g_V);
    cudaGetSymbolAddress((void**)&Yb, g_Y);
    cudaGetSymbolAddress((void**)&Sb, g_DS);

    // Fused Q/K/V projections in one launch (fills the grid)
    qkv_gemm<<<dim3(NTOK / 128, 12), 128>>>(X, Wq, Wk, Wv, Qb, Kb, Vb);

    // Chunked linear attention
    float* kv_out = (out_size >= OUT_ELEMS + KV_ELEMS) ? (out + OUT_ELEMS) : nullptr;
    state_kernel<<<dim3(NCHUNK, BATCH * NHEADS, 2), 256>>>(Kb, Vb, Sb);
    scan_kernel<<<dim3((SDF + 255) / 256, BATCH * NHEADS), 256>>>(Sb, kv_out);
    attn_out_kernel<<<dim3(NCHUNK, BATCH * NHEADS), 256>>>(Qb, Kb, Vb, Sb, g, Yb);

    // Output projection
    tgemm_nt<<<dim3(NTOK / 128, DMODEL / 128), 128>>>(Yb, Wo, out, NTOK, DMODEL, DMODEL);
}